// round 1
// baseline (speedup 1.0000x reference)
#include <cuda_runtime.h>
#include <math.h>

// Problem constants
#define B_   8
#define S_   512
#define D_   512
#define H_   8
#define HID_ 2048
#define DIM_ 64
#define ROWS_ (B_ * S_)        // 4096
#define QKV_N_ (3 * D_)        // 1536
#define EPS_ 0.001f

// ---------------------------------------------------------------------------
// Scratch (device globals; no allocation allowed)
// ---------------------------------------------------------------------------
__device__ float g_h[ROWS_ * D_];        // LN output        (8 MB)
__device__ float g_act[ROWS_ * HID_];    // MLP hidden       (32 MB)
__device__ float g_qkv[ROWS_ * QKV_N_];  // fused qkv        (24 MB)
__device__ float g_vres[ROWS_ * D_];     // values + attn    (8 MB)

// ---------------------------------------------------------------------------
// LayerNorm: one block per row, 128 threads, D=512 (float4 per thread)
// ---------------------------------------------------------------------------
__global__ void ln_kernel(const float* __restrict__ x,
                          const float* __restrict__ g,
                          const float* __restrict__ b,
                          float* __restrict__ y) {
    int row = blockIdx.x;
    int t   = threadIdx.x;  // 0..127
    const float4* xr = (const float4*)(x + (size_t)row * D_);
    float4 v = xr[t];
    float s  = v.x + v.y + v.z + v.w;
    float ss = v.x * v.x + v.y * v.y + v.z * v.z + v.w * v.w;
#pragma unroll
    for (int o = 16; o; o >>= 1) {
        s  += __shfl_xor_sync(0xffffffffu, s,  o);
        ss += __shfl_xor_sync(0xffffffffu, ss, o);
    }
    __shared__ float sm[4], sm2[4];
    int w = t >> 5;
    if ((t & 31) == 0) { sm[w] = s; sm2[w] = ss; }
    __syncthreads();
    float tot = sm[0] + sm[1] + sm[2] + sm[3];
    float tot2 = sm2[0] + sm2[1] + sm2[2] + sm2[3];
    float mean = tot * (1.0f / D_);
    float var  = tot2 * (1.0f / D_) - mean * mean;
    float rstd = rsqrtf(var + EPS_);

    int c = t * 4;
    float4 gv = *(const float4*)(g + c);
    float4 bv = *(const float4*)(b + c);
    float4 o;
    o.x = (v.x - mean) * rstd * gv.x + bv.x;
    o.y = (v.y - mean) * rstd * gv.y + bv.y;
    o.z = (v.z - mean) * rstd * gv.z + bv.z;
    o.w = (v.w - mean) * rstd * gv.w + bv.w;
    *(float4*)(y + (size_t)row * D_ + c) = o;
}

// ---------------------------------------------------------------------------
// Tiled SGEMM: C[M,N] = A[M,K] @ B[K,N] + bias  (+relu | +residual)
// BM=BN=128, BK=16, 256 threads, 8x8 per-thread tile.
// EPI: 0 = bias, 1 = bias+relu, 2 = bias+residual
// ---------------------------------------------------------------------------
template <int EPI>
__global__ void __launch_bounds__(256, 2)
sgemm_kernel(const float* __restrict__ A, const float* __restrict__ Bm,
             const float* __restrict__ bias, const float* __restrict__ res,
             float* __restrict__ C, int M, int N, int K) {
    __shared__ float As[16][128];
    __shared__ float Bs[16][128];

    int tid = threadIdx.x;
    int tr = tid >> 4;        // 0..15
    int tc = tid & 15;        // 0..15
    int m0 = blockIdx.y * 128;
    int n0 = blockIdx.x * 128;

    int ar  = tid >> 2;       // 0..63 (A row within tile, +64 on second)
    int ac4 = tid & 3;        // float4 col in k
    int bkr = tid >> 5;       // 0..7  (B k-row, +8 on second)
    int bc4 = tid & 31;       // float4 col in n

    float acc[8][8];
#pragma unroll
    for (int i = 0; i < 8; i++)
#pragma unroll
        for (int j = 0; j < 8; j++) acc[i][j] = 0.0f;

    for (int k0 = 0; k0 < K; k0 += 16) {
        float4 a0 = *(const float4*)(A + (size_t)(m0 + ar) * K + k0 + ac4 * 4);
        float4 a1 = *(const float4*)(A + (size_t)(m0 + ar + 64) * K + k0 + ac4 * 4);
        float4 b0 = *(const float4*)(Bm + (size_t)(k0 + bkr) * N + n0 + bc4 * 4);
        float4 b1 = *(const float4*)(Bm + (size_t)(k0 + bkr + 8) * N + n0 + bc4 * 4);
        __syncthreads();
        As[ac4 * 4 + 0][ar] = a0.x;  As[ac4 * 4 + 1][ar] = a0.y;
        As[ac4 * 4 + 2][ar] = a0.z;  As[ac4 * 4 + 3][ar] = a0.w;
        As[ac4 * 4 + 0][ar + 64] = a1.x;  As[ac4 * 4 + 1][ar + 64] = a1.y;
        As[ac4 * 4 + 2][ar + 64] = a1.z;  As[ac4 * 4 + 3][ar + 64] = a1.w;
        *(float4*)&Bs[bkr][bc4 * 4]     = b0;
        *(float4*)&Bs[bkr + 8][bc4 * 4] = b1;
        __syncthreads();
#pragma unroll
        for (int kk = 0; kk < 16; kk++) {
            float4 a40 = *(const float4*)&As[kk][tr * 8];
            float4 a41 = *(const float4*)&As[kk][tr * 8 + 4];
            float4 b40 = *(const float4*)&Bs[kk][tc * 8];
            float4 b41 = *(const float4*)&Bs[kk][tc * 8 + 4];
            float ra[8] = {a40.x, a40.y, a40.z, a40.w, a41.x, a41.y, a41.z, a41.w};
            float rb[8] = {b40.x, b40.y, b40.z, b40.w, b41.x, b41.y, b41.z, b41.w};
#pragma unroll
            for (int i = 0; i < 8; i++)
#pragma unroll
                for (int j = 0; j < 8; j++) acc[i][j] += ra[i] * rb[j];
        }
    }

#pragma unroll
    for (int i = 0; i < 8; i++) {
        size_t r = m0 + tr * 8 + i;
#pragma unroll
        for (int j = 0; j < 8; j += 4) {
            int c = n0 + tc * 8 + j;
            float4 bb = *(const float4*)(bias + c);
            float4 o;
            o.x = acc[i][j + 0] + bb.x;
            o.y = acc[i][j + 1] + bb.y;
            o.z = acc[i][j + 2] + bb.z;
            o.w = acc[i][j + 3] + bb.w;
            if (EPI == 1) {
                o.x = fmaxf(o.x, 0.0f); o.y = fmaxf(o.y, 0.0f);
                o.z = fmaxf(o.z, 0.0f); o.w = fmaxf(o.w, 0.0f);
            }
            if (EPI == 2) {
                float4 rv = *(const float4*)(res + r * N + c);
                o.x += rv.x; o.y += rv.y; o.z += rv.z; o.w += rv.w;
            }
            *(float4*)(C + r * N + c) = o;
        }
    }
}

// ---------------------------------------------------------------------------
// Flash attention with relative-position bias (NUM_POS=1, causal).
// Under the causal mask, bias(b,h,q,k) = q·w0 for k<q, q·w1 for k==q,
// where wm = (Wp[m] + bp).reshape(H,DIM)[h].
// Block: (qt, h, b), 256 threads, 64x64 tiles, 4x4 per-thread.
// Writes vres = values + attn_out.
// ---------------------------------------------------------------------------
#define LDT 68  // padded tile leading dim (multiple of 4, conflict-reducing)

__global__ void __launch_bounds__(256)
attn_kernel(const float* __restrict__ qkv, const float* __restrict__ values,
            const float* __restrict__ Wp, const float* __restrict__ bp,
            float* __restrict__ vres) {
    extern __shared__ float sh[];
    float* Qs = sh;
    float* Ks = Qs + 64 * LDT;
    float* Vs = Ks + 64 * LDT;
    float* Ps = Vs + 64 * LDT;
    float* bq = Ps + 64 * LDT;  // 128 floats: [row][m]

    int qt = blockIdx.x, h = blockIdx.y, b = blockIdx.z;
    int tid = threadIdx.x;
    int ty = tid >> 4, tx = tid & 15;

    // Load Q tile (64 rows x 64 cols)
#pragma unroll
    for (int it = 0; it < 4; it++) {
        int idx = tid + it * 256;
        int r = idx >> 4, c4 = idx & 15;
        const float* base = qkv + (size_t)(b * S_ + qt * 64 + r) * QKV_N_ + h * 192;
        *(float4*)&Qs[r * LDT + c4 * 4] = *(const float4*)(base + c4 * 4);
    }
    __syncthreads();

    // Per-row bias scalars bq[row][m], m in {0 (k<q), 1 (k==q)}
    if (tid < 128) {
        int row = tid >> 1, m = tid & 1;
        float s = 0.0f;
        const float* wrow = Wp + m * D_ + h * DIM_;
        const float* brow = bp + h * DIM_;
#pragma unroll 8
        for (int d = 0; d < 64; d++) s += Qs[row * LDT + d] * (wrow[d] + brow[d]);
        bq[row * 2 + m] = s;
    }

    float m_i[4], l_i[4], O[4][4];
#pragma unroll
    for (int i = 0; i < 4; i++) {
        m_i[i] = -1e30f; l_i[i] = 0.0f;
#pragma unroll
        for (int j = 0; j < 4; j++) O[i][j] = 0.0f;
    }

    for (int kt = 0; kt <= qt; kt++) {
        __syncthreads();  // prior use of Ks/Vs/Ps done (also covers bq on kt=0)
#pragma unroll
        for (int it = 0; it < 4; it++) {
            int idx = tid + it * 256;
            int r = idx >> 4, c4 = idx & 15;
            const float* base = qkv + (size_t)(b * S_ + kt * 64 + r) * QKV_N_ + h * 192;
            *(float4*)&Ks[r * LDT + c4 * 4] = *(const float4*)(base + 64 + c4 * 4);
            *(float4*)&Vs[r * LDT + c4 * 4] = *(const float4*)(base + 128 + c4 * 4);
        }
        __syncthreads();

        // scores 4x4
        float s4[4][4];
#pragma unroll
        for (int i = 0; i < 4; i++)
#pragma unroll
            for (int j = 0; j < 4; j++) s4[i][j] = 0.0f;
#pragma unroll 4
        for (int d = 0; d < 64; d++) {
            float qa[4], kb[4];
#pragma unroll
            for (int i = 0; i < 4; i++) qa[i] = Qs[(ty * 4 + i) * LDT + d];
#pragma unroll
            for (int j = 0; j < 4; j++) kb[j] = Ks[(tx * 4 + j) * LDT + d];
#pragma unroll
            for (int i = 0; i < 4; i++)
#pragma unroll
                for (int j = 0; j < 4; j++) s4[i][j] += qa[i] * kb[j];
        }

        bool diag = (kt == qt);
#pragma unroll
        for (int i = 0; i < 4; i++) {
            int qg = qt * 64 + ty * 4 + i;
            float b0 = bq[(ty * 4 + i) * 2];
            float b1 = bq[(ty * 4 + i) * 2 + 1];
#pragma unroll
            for (int j = 0; j < 4; j++) {
                int kg = kt * 64 + tx * 4 + j;
                float v = s4[i][j] * 0.125f + ((kg == qg) ? b1 : b0);
                if (diag && kg > qg) v = -1e9f;
                s4[i][j] = v;
            }
        }

        // online softmax (row groups = 16 lanes within half-warp)
#pragma unroll
        for (int i = 0; i < 4; i++) {
            float rm = fmaxf(fmaxf(s4[i][0], s4[i][1]), fmaxf(s4[i][2], s4[i][3]));
#pragma unroll
            for (int o = 1; o < 16; o <<= 1)
                rm = fmaxf(rm, __shfl_xor_sync(0xffffffffu, rm, o, 16));
            float mn = fmaxf(m_i[i], rm);
            float sc = __expf(m_i[i] - mn);
            float ls = 0.0f;
#pragma unroll
            for (int j = 0; j < 4; j++) {
                float p = __expf(s4[i][j] - mn);
                s4[i][j] = p;
                ls += p;
            }
#pragma unroll
            for (int o = 1; o < 16; o <<= 1)
                ls += __shfl_xor_sync(0xffffffffu, ls, o, 16);
            l_i[i] = l_i[i] * sc + ls;
            m_i[i] = mn;
#pragma unroll
            for (int j = 0; j < 4; j++) {
                O[i][j] *= sc;
                Ps[(ty * 4 + i) * LDT + tx * 4 + j] = s4[i][j];
            }
        }
        __syncthreads();

        // O += P @ V
#pragma unroll 4
        for (int k = 0; k < 64; k++) {
            float pv[4], vv[4];
#pragma unroll
            for (int i = 0; i < 4; i++) pv[i] = Ps[(ty * 4 + i) * LDT + k];
#pragma unroll
            for (int j = 0; j < 4; j++) vv[j] = Vs[k * LDT + tx * 4 + j];
#pragma unroll
            for (int i = 0; i < 4; i++)
#pragma unroll
                for (int j = 0; j < 4; j++) O[i][j] += pv[i] * vv[j];
        }
    }

    // vres = values + O/l
#pragma unroll
    for (int i = 0; i < 4; i++) {
        size_t row = (size_t)(b * S_ + qt * 64 + ty * 4 + i);
        float inv = 1.0f / l_i[i];
#pragma unroll
        for (int j = 0; j < 4; j++) {
            int col = h * DIM_ + tx * 4 + j;
            vres[row * D_ + col] = values[row * D_ + col] + O[i][j] * inv;
        }
    }
}

// ---------------------------------------------------------------------------
// Launcher
// Inputs (metadata order): 0 values, 1 values_mask, 2 ln0_g, 3 ln0_b,
//   4 W0a, 5 b0a, 6 W0b, 7 b0b, 8 Wp, 9 bp, 10 ln1_g, 11 ln1_b,
//   12 W1a, 13 b1a, 14 W1b, 15 b1b
// ---------------------------------------------------------------------------
extern "C" void kernel_launch(void* const* d_in, const int* in_sizes, int n_in,
                              void* d_out, int out_size) {
    (void)in_sizes; (void)n_in; (void)out_size;
    const float* values = (const float*)d_in[0];
    const float* ln0_g  = (const float*)d_in[2];
    const float* ln0_b  = (const float*)d_in[3];
    const float* W0a    = (const float*)d_in[4];
    const float* b0a    = (const float*)d_in[5];
    const float* W0b    = (const float*)d_in[6];
    const float* b0b    = (const float*)d_in[7];
    const float* Wp     = (const float*)d_in[8];
    const float* bp     = (const float*)d_in[9];
    const float* ln1_g  = (const float*)d_in[10];
    const float* ln1_b  = (const float*)d_in[11];
    const float* W1a    = (const float*)d_in[12];
    const float* b1a    = (const float*)d_in[13];
    const float* W1b    = (const float*)d_in[14];
    const float* b1b    = (const float*)d_in[15];
    float* out = (float*)d_out;

    float *ph, *pact, *pqkv, *pvres;
    cudaGetSymbolAddress((void**)&ph,    g_h);
    cudaGetSymbolAddress((void**)&pact,  g_act);
    cudaGetSymbolAddress((void**)&pqkv,  g_qkv);
    cudaGetSymbolAddress((void**)&pvres, g_vres);

    // attention dynamic smem
    int attn_smem = (4 * 64 * LDT + 128) * (int)sizeof(float);
    cudaFuncSetAttribute(attn_kernel, cudaFuncAttributeMaxDynamicSharedMemorySize,
                         attn_smem);

    // 1) LN0
    ln_kernel<<<ROWS_, 128>>>(values, ln0_g, ln0_b, ph);
    // 2) act = relu(h @ W0a + b0a)   [4096,512]x[512,2048]
    sgemm_kernel<1><<<dim3(HID_ / 128, ROWS_ / 128), 256>>>(
        ph, W0a, b0a, nullptr, pact, ROWS_, HID_, D_);
    // 3) qkv = act @ W0b + b0b       [4096,2048]x[2048,1536]
    sgemm_kernel<0><<<dim3(QKV_N_ / 128, ROWS_ / 128), 256>>>(
        pact, W0b, b0b, nullptr, pqkv, ROWS_, QKV_N_, HID_);
    // 4) attention + residual -> vres
    attn_kernel<<<dim3(S_ / 64, H_, B_), 256, attn_smem>>>(
        pqkv, values, Wp, bp, pvres);
    // 5) LN1
    ln_kernel<<<ROWS_, 128>>>(pvres, ln1_g, ln1_b, ph);
    // 6) act = relu(h @ W1a + b1a)   [4096,512]x[512,2048]
    sgemm_kernel<1><<<dim3(HID_ / 128, ROWS_ / 128), 256>>>(
        ph, W1a, b1a, nullptr, pact, ROWS_, HID_, D_);
    // 7) out = vres + act @ W1b + b1b   [4096,2048]x[2048,512]
    sgemm_kernel<2><<<dim3(D_ / 128, ROWS_ / 128), 256>>>(
        pact, W1b, b1b, pvres, out, ROWS_, D_, HID_);
}

// round 3
// speedup vs baseline: 3.7730x; 3.7730x over previous
#include <cuda_runtime.h>
#include <cuda_fp16.h>
#include <math.h>
#include <cstdint>

// Problem constants
#define B_   8
#define S_   512
#define D_   512
#define H_   8
#define HID_ 2048
#define DIM_ 64
#define ROWS_ (B_ * S_)        // 4096
#define QKV_N_ (3 * D_)        // 1536
#define EPS_ 0.001f

// ---------------------------------------------------------------------------
// Scratch (device globals; no allocation allowed)
// ---------------------------------------------------------------------------
__device__ __align__(16) half  g_h[ROWS_ * D_];        // LN output (half)
__device__ __align__(16) half  g_act[ROWS_ * HID_];    // MLP hidden (half)
__device__ __align__(16) float g_qkv[ROWS_ * QKV_N_];  // fused qkv (fp32)
__device__ __align__(16) float g_vres[ROWS_ * D_];     // values + attn
// transposed weights (B^T, [N,K] K-major, half) for mma.sync
__device__ __align__(16) half g_wt0a[HID_ * D_];
__device__ __align__(16) half g_wt0b[QKV_N_ * HID_];
__device__ __align__(16) half g_wt1a[HID_ * D_];
__device__ __align__(16) half g_wt1b[D_ * HID_];

// ---------------------------------------------------------------------------
// helpers
// ---------------------------------------------------------------------------
__device__ __forceinline__ uint32_t smem_u32(const void* p) {
    uint32_t a;
    asm("{ .reg .u64 t; cvta.to.shared.u64 t, %1; cvt.u32.u64 %0, t; }"
        : "=r"(a) : "l"(p));
    return a;
}
__device__ __forceinline__ void cp_async16(uint32_t d, const void* s) {
    asm volatile("cp.async.cg.shared.global [%0], [%1], 16;"
                 :: "r"(d), "l"(s) : "memory");
}
__device__ __forceinline__ void mma16816(float* c, uint32_t a0, uint32_t a1,
                                         uint32_t a2, uint32_t a3,
                                         uint32_t b0, uint32_t b1) {
    asm volatile(
        "mma.sync.aligned.m16n8k16.row.col.f32.f16.f16.f32 "
        "{%0,%1,%2,%3}, {%4,%5,%6,%7}, {%8,%9}, {%0,%1,%2,%3};"
        : "+f"(c[0]), "+f"(c[1]), "+f"(c[2]), "+f"(c[3])
        : "r"(a0), "r"(a1), "r"(a2), "r"(a3), "r"(b0), "r"(b1));
}

// ---------------------------------------------------------------------------
// Weight transpose + fp32->fp16: src[K,N] fp32 -> dst[N,K] half
// ---------------------------------------------------------------------------
__global__ void transpose_kernel(const float* __restrict__ src,
                                 half* __restrict__ dst, int K, int N) {
    __shared__ float t[32][33];
    int bn = blockIdx.x * 32, bk = blockIdx.y * 32;
    int x = bn + threadIdx.x;
#pragma unroll
    for (int i = 0; i < 32; i += 8)
        t[threadIdx.y + i][threadIdx.x] = src[(size_t)(bk + threadIdx.y + i) * N + x];
    __syncthreads();
    int xo = bk + threadIdx.x;
#pragma unroll
    for (int i = 0; i < 32; i += 8)
        dst[(size_t)(bn + threadIdx.y + i) * K + xo] =
            __float2half_rn(t[threadIdx.x][threadIdx.y + i]);
}

// ---------------------------------------------------------------------------
// HMMA fp16 GEMM: C[M,N] = A[M,K](half) @ Bt[N,K](half)^T + bias
// BM=BN=128, BK=64, 256 threads (8 warps, 2x4), warp tile 64x32.
// Double-buffered cp.async. smem rows padded to 72 halves (conflict-free).
// EPI: 0 = bias -> float out; 1 = bias+relu -> half out; 2 = bias+res -> float
// ---------------------------------------------------------------------------
#define LDH 72          // halves per smem row
#define TILE_H (128 * LDH)  // halves per tile buffer

template <int EPI>
__global__ void __launch_bounds__(256)
mma_gemm(const half* __restrict__ A, const half* __restrict__ Bt,
         const float* __restrict__ bias, const float* __restrict__ res,
         void* __restrict__ Cout, int N, int K) {
    extern __shared__ char smem[];
    half* As = (half*)smem;            // [2][128][LDH]
    half* Bs = As + 2 * TILE_H;
    uint32_t sA = smem_u32(As);
    uint32_t sB = smem_u32(Bs);

    int tid = threadIdx.x;
    int wid = tid >> 5, lane = tid & 31;
    int wm = wid >> 2, wn = wid & 3;
    int g = lane >> 2, tg = lane & 3;
    int m0 = blockIdx.y * 128, n0 = blockIdx.x * 128;

    float acc[4][4][4];
#pragma unroll
    for (int i = 0; i < 4; i++)
#pragma unroll
        for (int j = 0; j < 4; j++)
#pragma unroll
            for (int r = 0; r < 4; r++) acc[i][j][r] = 0.0f;

    // tile loader: 128 rows x 64 halves (=128B) per tile, 16B chunks
    auto load_tiles = [&](int kt, int buf) {
        uint32_t da = sA + buf * TILE_H * 2;
        uint32_t db = sB + buf * TILE_H * 2;
#pragma unroll
        for (int p = 0; p < 4; p++) {
            int idx = tid + p * 256;
            int r = idx >> 3, c = idx & 7;
            cp_async16(da + (r * LDH + c * 8) * 2,
                       A + (size_t)(m0 + r) * K + kt * 64 + c * 8);
        }
#pragma unroll
        for (int p = 0; p < 4; p++) {
            int idx = tid + p * 256;
            int r = idx >> 3, c = idx & 7;
            cp_async16(db + (r * LDH + c * 8) * 2,
                       Bt + (size_t)(n0 + r) * K + kt * 64 + c * 8);
        }
        asm volatile("cp.async.commit_group;" ::: "memory");
    };

    const int KT = K / 64;
    load_tiles(0, 0);

    for (int kt = 0; kt < KT; kt++) {
        int buf = kt & 1;
        if (kt + 1 < KT) {
            load_tiles(kt + 1, buf ^ 1);
            asm volatile("cp.async.wait_group 1;" ::: "memory");
        } else {
            asm volatile("cp.async.wait_group 0;" ::: "memory");
        }
        __syncthreads();

        const half* Ab = As + buf * TILE_H;
        const half* Bb = Bs + buf * TILE_H;
#pragma unroll
        for (int ks = 0; ks < 4; ks++) {
            int k0 = ks * 16;
            uint32_t breg[4][2];
#pragma unroll
            for (int na = 0; na < 4; na++) {
                const half* bp = Bb + (wn * 32 + na * 8 + g) * LDH + k0 + 2 * tg;
                breg[na][0] = *(const uint32_t*)bp;
                breg[na][1] = *(const uint32_t*)(bp + 8);
            }
#pragma unroll
            for (int ma = 0; ma < 4; ma++) {
                const half* ap = Ab + (wm * 64 + ma * 16 + g) * LDH + k0 + 2 * tg;
                uint32_t a0 = *(const uint32_t*)ap;
                uint32_t a1 = *(const uint32_t*)(ap + 8 * LDH);
                uint32_t a2 = *(const uint32_t*)(ap + 8);
                uint32_t a3 = *(const uint32_t*)(ap + 8 * LDH + 8);
#pragma unroll
                for (int na = 0; na < 4; na++)
                    mma16816(acc[ma][na], a0, a1, a2, a3, breg[na][0], breg[na][1]);
            }
        }
        __syncthreads();
    }

    // epilogue
#pragma unroll
    for (int na = 0; na < 4; na++) {
        int col = n0 + wn * 32 + na * 8 + 2 * tg;
        float2 bb = *(const float2*)(bias + col);
#pragma unroll
        for (int ma = 0; ma < 4; ma++) {
            int row = m0 + wm * 64 + ma * 16 + g;
            float x0 = acc[ma][na][0] + bb.x;
            float x1 = acc[ma][na][1] + bb.y;
            float x2 = acc[ma][na][2] + bb.x;
            float x3 = acc[ma][na][3] + bb.y;
            if (EPI == 1) {
                x0 = fmaxf(x0, 0.0f); x1 = fmaxf(x1, 0.0f);
                x2 = fmaxf(x2, 0.0f); x3 = fmaxf(x3, 0.0f);
                half* C = (half*)Cout;
                *(half2*)(C + (size_t)row * N + col)       = __floats2half2_rn(x0, x1);
                *(half2*)(C + (size_t)(row + 8) * N + col) = __floats2half2_rn(x2, x3);
            } else if (EPI == 0) {
                float* C = (float*)Cout;
                float2 v0 = {x0, x1}, v1 = {x2, x3};
                *(float2*)(C + (size_t)row * N + col) = v0;
                *(float2*)(C + (size_t)(row + 8) * N + col) = v1;
            } else {
                float* C = (float*)Cout;
                float2 r0 = *(const float2*)(res + (size_t)row * N + col);
                float2 r1 = *(const float2*)(res + (size_t)(row + 8) * N + col);
                float2 v0 = {x0 + r0.x, x1 + r0.y};
                float2 v1 = {x2 + r1.x, x3 + r1.y};
                *(float2*)(C + (size_t)row * N + col) = v0;
                *(float2*)(C + (size_t)(row + 8) * N + col) = v1;
            }
        }
    }
}

// ---------------------------------------------------------------------------
// LayerNorm: one block per row, 128 threads, D=512; outputs HALF (rounded)
// ---------------------------------------------------------------------------
__global__ void ln_kernel(const float* __restrict__ x,
                          const float* __restrict__ g,
                          const float* __restrict__ b,
                          half* __restrict__ y) {
    int row = blockIdx.x;
    int t   = threadIdx.x;
    const float4* xr = (const float4*)(x + (size_t)row * D_);
    float4 v = xr[t];
    float s  = v.x + v.y + v.z + v.w;
    float ss = v.x * v.x + v.y * v.y + v.z * v.z + v.w * v.w;
#pragma unroll
    for (int o = 16; o; o >>= 1) {
        s  += __shfl_xor_sync(0xffffffffu, s,  o);
        ss += __shfl_xor_sync(0xffffffffu, ss, o);
    }
    __shared__ float sm[4], sm2[4];
    int w = t >> 5;
    if ((t & 31) == 0) { sm[w] = s; sm2[w] = ss; }
    __syncthreads();
    float tot = sm[0] + sm[1] + sm[2] + sm[3];
    float tot2 = sm2[0] + sm2[1] + sm2[2] + sm2[3];
    float mean = tot * (1.0f / D_);
    float var  = tot2 * (1.0f / D_) - mean * mean;
    float rstd = rsqrtf(var + EPS_);

    int c = t * 4;
    float4 gv = *(const float4*)(g + c);
    float4 bv = *(const float4*)(b + c);
    half* yr = y + (size_t)row * D_ + c;
    *(half2*)(yr)     = __floats2half2_rn((v.x - mean) * rstd * gv.x + bv.x,
                                          (v.y - mean) * rstd * gv.y + bv.y);
    *(half2*)(yr + 2) = __floats2half2_rn((v.z - mean) * rstd * gv.z + bv.z,
                                          (v.w - mean) * rstd * gv.w + bv.w);
}

// ---------------------------------------------------------------------------
// Flash attention with relative-position bias (NUM_POS=1, causal), fp32.
// bias(b,h,q,k) = q.w0 for k<q, q.w1 for k==q, wm = (Wp[m]+bp).reshape(H,DIM)[h]
// ---------------------------------------------------------------------------
#define LDT 68

__global__ void __launch_bounds__(256)
attn_kernel(const float* __restrict__ qkv, const float* __restrict__ values,
            const float* __restrict__ Wp, const float* __restrict__ bp,
            float* __restrict__ vres) {
    extern __shared__ float sh[];
    float* Qs = sh;
    float* Ks = Qs + 64 * LDT;
    float* Vs = Ks + 64 * LDT;
    float* Ps = Vs + 64 * LDT;
    float* bq = Ps + 64 * LDT;

    int qt = blockIdx.x, h = blockIdx.y, b = blockIdx.z;
    int tid = threadIdx.x;
    int ty = tid >> 4, tx = tid & 15;

#pragma unroll
    for (int it = 0; it < 4; it++) {
        int idx = tid + it * 256;
        int r = idx >> 4, c4 = idx & 15;
        const float* base = qkv + (size_t)(b * S_ + qt * 64 + r) * QKV_N_ + h * 192;
        *(float4*)&Qs[r * LDT + c4 * 4] = *(const float4*)(base + c4 * 4);
    }
    __syncthreads();

    if (tid < 128) {
        int row = tid >> 1, m = tid & 1;
        float s = 0.0f;
        const float* wrow = Wp + m * D_ + h * DIM_;
        const float* brow = bp + h * DIM_;
#pragma unroll 8
        for (int d = 0; d < 64; d++) s += Qs[row * LDT + d] * (wrow[d] + brow[d]);
        bq[row * 2 + m] = s;
    }

    float m_i[4], l_i[4], O[4][4];
#pragma unroll
    for (int i = 0; i < 4; i++) {
        m_i[i] = -1e30f; l_i[i] = 0.0f;
#pragma unroll
        for (int j = 0; j < 4; j++) O[i][j] = 0.0f;
    }

    for (int kt = 0; kt <= qt; kt++) {
        __syncthreads();
#pragma unroll
        for (int it = 0; it < 4; it++) {
            int idx = tid + it * 256;
            int r = idx >> 4, c4 = idx & 15;
            const float* base = qkv + (size_t)(b * S_ + kt * 64 + r) * QKV_N_ + h * 192;
            *(float4*)&Ks[r * LDT + c4 * 4] = *(const float4*)(base + 64 + c4 * 4);
            *(float4*)&Vs[r * LDT + c4 * 4] = *(const float4*)(base + 128 + c4 * 4);
        }
        __syncthreads();

        float s4[4][4];
#pragma unroll
        for (int i = 0; i < 4; i++)
#pragma unroll
            for (int j = 0; j < 4; j++) s4[i][j] = 0.0f;
#pragma unroll 4
        for (int d = 0; d < 64; d++) {
            float qa[4], kb[4];
#pragma unroll
            for (int i = 0; i < 4; i++) qa[i] = Qs[(ty * 4 + i) * LDT + d];
#pragma unroll
            for (int j = 0; j < 4; j++) kb[j] = Ks[(tx * 4 + j) * LDT + d];
#pragma unroll
            for (int i = 0; i < 4; i++)
#pragma unroll
                for (int j = 0; j < 4; j++) s4[i][j] += qa[i] * kb[j];
        }

        bool diag = (kt == qt);
#pragma unroll
        for (int i = 0; i < 4; i++) {
            int qg = qt * 64 + ty * 4 + i;
            float b0 = bq[(ty * 4 + i) * 2];
            float b1 = bq[(ty * 4 + i) * 2 + 1];
#pragma unroll
            for (int j = 0; j < 4; j++) {
                int kg = kt * 64 + tx * 4 + j;
                float v = s4[i][j] * 0.125f + ((kg == qg) ? b1 : b0);
                if (diag && kg > qg) v = -1e9f;
                s4[i][j] = v;
            }
        }

#pragma unroll
        for (int i = 0; i < 4; i++) {
            float rm = fmaxf(fmaxf(s4[i][0], s4[i][1]), fmaxf(s4[i][2], s4[i][3]));
#pragma unroll
            for (int o = 1; o < 16; o <<= 1)
                rm = fmaxf(rm, __shfl_xor_sync(0xffffffffu, rm, o, 16));
            float mn = fmaxf(m_i[i], rm);
            float sc = __expf(m_i[i] - mn);
            float ls = 0.0f;
#pragma unroll
            for (int j = 0; j < 4; j++) {
                float p = __expf(s4[i][j] - mn);
                s4[i][j] = p;
                ls += p;
            }
#pragma unroll
            for (int o = 1; o < 16; o <<= 1)
                ls += __shfl_xor_sync(0xffffffffu, ls, o, 16);
            l_i[i] = l_i[i] * sc + ls;
            m_i[i] = mn;
#pragma unroll
            for (int j = 0; j < 4; j++) {
                O[i][j] *= sc;
                Ps[(ty * 4 + i) * LDT + tx * 4 + j] = s4[i][j];
            }
        }
        __syncthreads();

#pragma unroll 4
        for (int k = 0; k < 64; k++) {
            float pv[4], vv[4];
#pragma unroll
            for (int i = 0; i < 4; i++) pv[i] = Ps[(ty * 4 + i) * LDT + k];
#pragma unroll
            for (int j = 0; j < 4; j++) vv[j] = Vs[k * LDT + tx * 4 + j];
#pragma unroll
            for (int i = 0; i < 4; i++)
#pragma unroll
                for (int j = 0; j < 4; j++) O[i][j] += pv[i] * vv[j];
        }
    }

#pragma unroll
    for (int i = 0; i < 4; i++) {
        size_t row = (size_t)(b * S_ + qt * 64 + ty * 4 + i);
        float inv = 1.0f / l_i[i];
#pragma unroll
        for (int j = 0; j < 4; j++) {
            int col = h * DIM_ + tx * 4 + j;
            vres[row * D_ + col] = values[row * D_ + col] + O[i][j] * inv;
        }
    }
}

// ---------------------------------------------------------------------------
// Launcher
// ---------------------------------------------------------------------------
extern "C" void kernel_launch(void* const* d_in, const int* in_sizes, int n_in,
                              void* d_out, int out_size) {
    (void)in_sizes; (void)n_in; (void)out_size;
    const float* values = (const float*)d_in[0];
    const float* ln0_g  = (const float*)d_in[2];
    const float* ln0_b  = (const float*)d_in[3];
    const float* W0a    = (const float*)d_in[4];
    const float* b0a    = (const float*)d_in[5];
    const float* W0b    = (const float*)d_in[6];
    const float* b0b    = (const float*)d_in[7];
    const float* Wp     = (const float*)d_in[8];
    const float* bp     = (const float*)d_in[9];
    const float* ln1_g  = (const float*)d_in[10];
    const float* ln1_b  = (const float*)d_in[11];
    const float* W1a    = (const float*)d_in[12];
    const float* b1a    = (const float*)d_in[13];
    const float* W1b    = (const float*)d_in[14];
    const float* b1b    = (const float*)d_in[15];
    float* out = (float*)d_out;

    half *ph, *pact, *pwt0a, *pwt0b, *pwt1a, *pwt1b;
    float *pqkv, *pvres;
    cudaGetSymbolAddress((void**)&ph,    g_h);
    cudaGetSymbolAddress((void**)&pact,  g_act);
    cudaGetSymbolAddress((void**)&pqkv,  g_qkv);
    cudaGetSymbolAddress((void**)&pvres, g_vres);
    cudaGetSymbolAddress((void**)&pwt0a, g_wt0a);
    cudaGetSymbolAddress((void**)&pwt0b, g_wt0b);
    cudaGetSymbolAddress((void**)&pwt1a, g_wt1a);
    cudaGetSymbolAddress((void**)&pwt1b, g_wt1b);

    int gemm_smem = 2 * 2 * TILE_H * 2;  // 73728 bytes
    cudaFuncSetAttribute(mma_gemm<0>, cudaFuncAttributeMaxDynamicSharedMemorySize, gemm_smem);
    cudaFuncSetAttribute(mma_gemm<1>, cudaFuncAttributeMaxDynamicSharedMemorySize, gemm_smem);
    cudaFuncSetAttribute(mma_gemm<2>, cudaFuncAttributeMaxDynamicSharedMemorySize, gemm_smem);
    int attn_smem = (4 * 64 * LDT + 128) * (int)sizeof(float);
    cudaFuncSetAttribute(attn_kernel, cudaFuncAttributeMaxDynamicSharedMemorySize, attn_smem);

    // 0) transpose weights to [N,K] half
    transpose_kernel<<<dim3(HID_ / 32, D_ / 32), dim3(32, 8)>>>(W0a, pwt0a, D_, HID_);
    transpose_kernel<<<dim3(QKV_N_ / 32, HID_ / 32), dim3(32, 8)>>>(W0b, pwt0b, HID_, QKV_N_);
    transpose_kernel<<<dim3(HID_ / 32, D_ / 32), dim3(32, 8)>>>(W1a, pwt1a, D_, HID_);
    transpose_kernel<<<dim3(D_ / 32, HID_ / 32), dim3(32, 8)>>>(W1b, pwt1b, HID_, D_);

    // 1) LN0 -> half
    ln_kernel<<<ROWS_, 128>>>(values, ln0_g, ln0_b, ph);
    // 2) act = relu(h @ W0a + b0a) -> half   [4096,512]x[512,2048]
    mma_gemm<1><<<dim3(HID_ / 128, ROWS_ / 128), 256, gemm_smem>>>(
        ph, pwt0a, b0a, nullptr, pact, HID_, D_);
    // 3) qkv = act @ W0b + b0b -> float      [4096,2048]x[2048,1536]
    mma_gemm<0><<<dim3(QKV_N_ / 128, ROWS_ / 128), 256, gemm_smem>>>(
        pact, pwt0b, b0b, nullptr, pqkv, QKV_N_, HID_);
    // 4) attention + residual -> vres
    attn_kernel<<<dim3(S_ / 64, H_, B_), 256, attn_smem>>>(
        pqkv, values, Wp, bp, pvres);
    // 5) LN1 -> half
    ln_kernel<<<ROWS_, 128>>>(pvres, ln1_g, ln1_b, ph);
    // 6) act = relu(h @ W1a + b1a) -> half
    mma_gemm<1><<<dim3(HID_ / 128, ROWS_ / 128), 256, gemm_smem>>>(
        ph, pwt1a, b1a, nullptr, pact, HID_, D_);
    // 7) out = vres + act @ W1b + b1b -> float
    mma_gemm<2><<<dim3(D_ / 128, ROWS_ / 128), 256, gemm_smem>>>(
        pact, pwt1b, b1b, pvres, out, D_, HID_);
}

// round 6
// speedup vs baseline: 5.7863x; 1.5336x over previous
#include <cuda_runtime.h>
#include <cuda_fp16.h>
#include <math.h>
#include <cstdint>

// Problem constants
#define B_   8
#define S_   512
#define D_   512
#define H_   8
#define HID_ 2048
#define DIM_ 64
#define ROWS_ (B_ * S_)        // 4096
#define QKV_N_ (3 * D_)        // 1536
#define EPS_ 0.001f

// ---------------------------------------------------------------------------
// Scratch (device globals; no allocation allowed)
// ---------------------------------------------------------------------------
__device__ __align__(16) half  g_h[ROWS_ * D_];        // LN output (half)
__device__ __align__(16) half  g_act[ROWS_ * HID_];    // MLP hidden (half)
__device__ __align__(16) half  g_qkv[ROWS_ * QKV_N_];  // fused qkv (half)
__device__ __align__(16) float g_vres[ROWS_ * D_];     // values + attn
// transposed weights (B^T, [N,K] K-major, half) for mma.sync
__device__ __align__(16) half g_wt0a[HID_ * D_];
__device__ __align__(16) half g_wt0b[QKV_N_ * HID_];
__device__ __align__(16) half g_wt1a[HID_ * D_];
__device__ __align__(16) half g_wt1b[D_ * HID_];

// ---------------------------------------------------------------------------
// helpers
// ---------------------------------------------------------------------------
__device__ __forceinline__ void cp_async16(uint32_t d, const void* s) {
    asm volatile("cp.async.cg.shared.global [%0], [%1], 16;"
                 :: "r"(d), "l"(s) : "memory");
}
__device__ __forceinline__ uint32_t smem_u32(const void* p) {
    uint32_t a;
    asm("{ .reg .u64 t; cvta.to.shared.u64 t, %1; cvt.u32.u64 %0, t; }"
        : "=r"(a) : "l"(p));
    return a;
}
__device__ __forceinline__ uint32_t h2_as_u32(half2 h) {
    union { half2 h; uint32_t u; } cvt;
    cvt.h = h;
    return cvt.u;
}
__device__ __forceinline__ void mma16816(float* c, uint32_t a0, uint32_t a1,
                                         uint32_t a2, uint32_t a3,
                                         uint32_t b0, uint32_t b1) {
    asm volatile(
        "mma.sync.aligned.m16n8k16.row.col.f32.f16.f16.f32 "
        "{%0,%1,%2,%3}, {%4,%5,%6,%7}, {%8,%9}, {%0,%1,%2,%3};"
        : "+f"(c[0]), "+f"(c[1]), "+f"(c[2]), "+f"(c[3])
        : "r"(a0), "r"(a1), "r"(a2), "r"(a3), "r"(b0), "r"(b1));
}

// ---------------------------------------------------------------------------
// Weight transpose + fp32->fp16: src[K,N] fp32 -> dst[N,K] half
// ---------------------------------------------------------------------------
__global__ void transpose_kernel(const float* __restrict__ src,
                                 half* __restrict__ dst, int K, int N) {
    __shared__ float t[32][33];
    int bn = blockIdx.x * 32, bk = blockIdx.y * 32;
    int x = bn + threadIdx.x;
#pragma unroll
    for (int i = 0; i < 32; i += 8)
        t[threadIdx.y + i][threadIdx.x] = src[(size_t)(bk + threadIdx.y + i) * N + x];
    __syncthreads();
    int xo = bk + threadIdx.x;
#pragma unroll
    for (int i = 0; i < 32; i += 8)
        dst[(size_t)(bn + threadIdx.y + i) * K + xo] =
            __float2half_rn(t[threadIdx.x][threadIdx.y + i]);
}

// ---------------------------------------------------------------------------
// HMMA fp16 GEMM: C[M,N] = A[M,K](half) @ Bt[N,K](half)^T + bias
// BM=BN=128, BK=64, 256 threads (8 warps, 2x4), warp tile 64x32.
// EPI: 0 = bias -> half out; 1 = bias+relu -> half out; 2 = bias+res -> float
// ---------------------------------------------------------------------------
#define LDH 72
#define TILE_H (128 * LDH)

template <int EPI>
__global__ void __launch_bounds__(256)
mma_gemm(const half* __restrict__ A, const half* __restrict__ Bt,
         const float* __restrict__ bias, const float* __restrict__ res,
         void* __restrict__ Cout, int N, int K) {
    extern __shared__ char smem[];
    half* As = (half*)smem;
    half* Bs = As + 2 * TILE_H;
    uint32_t sA = smem_u32(As);
    uint32_t sB = smem_u32(Bs);

    int tid = threadIdx.x;
    int wid = tid >> 5, lane = tid & 31;
    int wm = wid >> 2, wn = wid & 3;
    int g = lane >> 2, tg = lane & 3;
    int m0 = blockIdx.y * 128, n0 = blockIdx.x * 128;

    float acc[4][4][4];
#pragma unroll
    for (int i = 0; i < 4; i++)
#pragma unroll
        for (int j = 0; j < 4; j++)
#pragma unroll
            for (int r = 0; r < 4; r++) acc[i][j][r] = 0.0f;

    auto load_tiles = [&](int kt, int buf) {
        uint32_t da = sA + buf * TILE_H * 2;
        uint32_t db = sB + buf * TILE_H * 2;
#pragma unroll
        for (int p = 0; p < 4; p++) {
            int idx = tid + p * 256;
            int r = idx >> 3, c = idx & 7;
            cp_async16(da + (r * LDH + c * 8) * 2,
                       A + (size_t)(m0 + r) * K + kt * 64 + c * 8);
        }
#pragma unroll
        for (int p = 0; p < 4; p++) {
            int idx = tid + p * 256;
            int r = idx >> 3, c = idx & 7;
            cp_async16(db + (r * LDH + c * 8) * 2,
                       Bt + (size_t)(n0 + r) * K + kt * 64 + c * 8);
        }
        asm volatile("cp.async.commit_group;" ::: "memory");
    };

    const int KT = K / 64;
    load_tiles(0, 0);

    for (int kt = 0; kt < KT; kt++) {
        int buf = kt & 1;
        if (kt + 1 < KT) {
            load_tiles(kt + 1, buf ^ 1);
            asm volatile("cp.async.wait_group 1;" ::: "memory");
        } else {
            asm volatile("cp.async.wait_group 0;" ::: "memory");
        }
        __syncthreads();

        const half* Ab = As + buf * TILE_H;
        const half* Bb = Bs + buf * TILE_H;
#pragma unroll
        for (int ks = 0; ks < 4; ks++) {
            int k0 = ks * 16;
            uint32_t breg[4][2];
#pragma unroll
            for (int na = 0; na < 4; na++) {
                const half* bp = Bb + (wn * 32 + na * 8 + g) * LDH + k0 + 2 * tg;
                breg[na][0] = *(const uint32_t*)bp;
                breg[na][1] = *(const uint32_t*)(bp + 8);
            }
#pragma unroll
            for (int ma = 0; ma < 4; ma++) {
                const half* ap = Ab + (wm * 64 + ma * 16 + g) * LDH + k0 + 2 * tg;
                uint32_t a0 = *(const uint32_t*)ap;
                uint32_t a1 = *(const uint32_t*)(ap + 8 * LDH);
                uint32_t a2 = *(const uint32_t*)(ap + 8);
                uint32_t a3 = *(const uint32_t*)(ap + 8 * LDH + 8);
#pragma unroll
                for (int na = 0; na < 4; na++)
                    mma16816(acc[ma][na], a0, a1, a2, a3, breg[na][0], breg[na][1]);
            }
        }
        __syncthreads();
    }

#pragma unroll
    for (int na = 0; na < 4; na++) {
        int col = n0 + wn * 32 + na * 8 + 2 * tg;
        float2 bb = *(const float2*)(bias + col);
#pragma unroll
        for (int ma = 0; ma < 4; ma++) {
            int row = m0 + wm * 64 + ma * 16 + g;
            float x0 = acc[ma][na][0] + bb.x;
            float x1 = acc[ma][na][1] + bb.y;
            float x2 = acc[ma][na][2] + bb.x;
            float x3 = acc[ma][na][3] + bb.y;
            if (EPI == 1) {
                x0 = fmaxf(x0, 0.0f); x1 = fmaxf(x1, 0.0f);
                x2 = fmaxf(x2, 0.0f); x3 = fmaxf(x3, 0.0f);
            }
            if (EPI == 0 || EPI == 1) {
                half* C = (half*)Cout;
                *(half2*)(C + (size_t)row * N + col)       = __floats2half2_rn(x0, x1);
                *(half2*)(C + (size_t)(row + 8) * N + col) = __floats2half2_rn(x2, x3);
            } else {
                float* C = (float*)Cout;
                float2 r0 = *(const float2*)(res + (size_t)row * N + col);
                float2 r1 = *(const float2*)(res + (size_t)(row + 8) * N + col);
                float2 v0 = {x0 + r0.x, x1 + r0.y};
                float2 v1 = {x2 + r1.x, x3 + r1.y};
                *(float2*)(C + (size_t)row * N + col) = v0;
                *(float2*)(C + (size_t)(row + 8) * N + col) = v1;
            }
        }
    }
}

// ---------------------------------------------------------------------------
// LayerNorm: one block per row, 128 threads, D=512; outputs HALF
// ---------------------------------------------------------------------------
__global__ void ln_kernel(const float* __restrict__ x,
                          const float* __restrict__ g,
                          const float* __restrict__ b,
                          half* __restrict__ y) {
    int row = blockIdx.x;
    int t   = threadIdx.x;
    const float4* xr = (const float4*)(x + (size_t)row * D_);
    float4 v = xr[t];
    float s  = v.x + v.y + v.z + v.w;
    float ss = v.x * v.x + v.y * v.y + v.z * v.z + v.w * v.w;
#pragma unroll
    for (int o = 16; o; o >>= 1) {
        s  += __shfl_xor_sync(0xffffffffu, s,  o);
        ss += __shfl_xor_sync(0xffffffffu, ss, o);
    }
    __shared__ float sm[4], sm2[4];
    int w = t >> 5;
    if ((t & 31) == 0) { sm[w] = s; sm2[w] = ss; }
    __syncthreads();
    float tot = sm[0] + sm[1] + sm[2] + sm[3];
    float tot2 = sm2[0] + sm2[1] + sm2[2] + sm2[3];
    float mean = tot * (1.0f / D_);
    float var  = tot2 * (1.0f / D_) - mean * mean;
    float rstd = rsqrtf(var + EPS_);

    int c = t * 4;
    float4 gv = *(const float4*)(g + c);
    float4 bv = *(const float4*)(b + c);
    half* yr = y + (size_t)row * D_ + c;
    *(half2*)(yr)     = __floats2half2_rn((v.x - mean) * rstd * gv.x + bv.x,
                                          (v.y - mean) * rstd * gv.y + bv.y);
    *(half2*)(yr + 2) = __floats2half2_rn((v.z - mean) * rstd * gv.z + bv.z,
                                          (v.w - mean) * rstd * gv.w + bv.w);
}

// ---------------------------------------------------------------------------
// HMMA flash attention with relative-position bias (NUM_POS=1, causal).
// Block = 64 q rows x (h, b); 128 threads (4 warps), warp owns 16 q rows.
// S = Q K^T via m16n8k16; P stays in registers (C-frag == A-frag layout);
// V transposed in smem once per K-tile for the PV mma.
// ---------------------------------------------------------------------------
#define ALD 72   // Qs/Ks/Vt row stride (halves)
#define VLD 72   // Vs staging row stride (halves; MUST be mult of 8 for uint4)

__global__ void __launch_bounds__(128)
attn_mma_kernel(const half* __restrict__ qkv, const float* __restrict__ values,
                const float* __restrict__ Wp, const float* __restrict__ bp,
                float* __restrict__ vres) {
    __shared__ half Qs[64][ALD];
    __shared__ half Ks[64][ALD];
    __shared__ half Vs[64][VLD];
    __shared__ half Vt[64][ALD];
    __shared__ float bq[64][2];

    int qt = blockIdx.x, h = blockIdx.y, b = blockIdx.z;
    int tid = threadIdx.x;
    int w = tid >> 5, lane = tid & 31;
    int g = lane >> 2, tg = lane & 3;

    // load Q tile: 64 rows x 64 halves (8 uint4/row)
#pragma unroll
    for (int it = 0; it < 4; it++) {
        int job = tid + it * 128;
        int r = job >> 3, c = job & 7;
        *(uint4*)&Qs[r][c * 8] = *(const uint4*)(
            qkv + (size_t)(b * S_ + qt * 64 + r) * QKV_N_ + h * 192 + c * 8);
    }
    __syncthreads();

    // per-row bias scalars: bq[row][0] (k<q), bq[row][1] (k==q)
    {
        int row = tid >> 1, m = tid & 1;
        float s = 0.0f;
        const float* wrow = Wp + m * D_ + h * DIM_;
        const float* brow = bp + h * DIM_;
#pragma unroll 8
        for (int d = 0; d < 64; d++)
            s += __half2float(Qs[row][d]) * (wrow[d] + brow[d]);
        bq[row][m] = s;
    }

    // hoist Q a-frags: aq[ks][0..3]
    uint32_t aq[4][4];
#pragma unroll
    for (int ks = 0; ks < 4; ks++) {
        const half* ap = &Qs[16 * w + g][16 * ks + 2 * tg];
        aq[ks][0] = *(const uint32_t*)ap;
        aq[ks][1] = *(const uint32_t*)(ap + 8 * ALD);
        aq[ks][2] = *(const uint32_t*)(ap + 8);
        aq[ks][3] = *(const uint32_t*)(ap + 8 * ALD + 8);
    }

    float m_i[2] = {-1e30f, -1e30f};
    float l_i[2] = {0.0f, 0.0f};
    float O[8][4];
#pragma unroll
    for (int nd = 0; nd < 8; nd++)
#pragma unroll
        for (int r = 0; r < 4; r++) O[nd][r] = 0.0f;

    int qg0 = qt * 64 + 16 * w + g;
    int qg1 = qg0 + 8;

    for (int kt = 0; kt <= qt; kt++) {
        __syncthreads();  // Ks/Vs/Vt free; bq ready (kt==0)
        // load K, V tiles (coalesced, 8 uint4 per row)
#pragma unroll
        for (int it = 0; it < 4; it++) {
            int job = tid + it * 128;
            int r = job >> 3, c = job & 7;
            const half* base = qkv + (size_t)(b * S_ + kt * 64 + r) * QKV_N_ + h * 192;
            *(uint4*)&Ks[r][c * 8] = *(const uint4*)(base + 64 + c * 8);
            *(uint4*)&Vs[r][c * 8] = *(const uint4*)(base + 128 + c * 8);
        }
        __syncthreads();

        // transpose Vs -> Vt (Vt[d][k] = Vs[k][d])
#pragma unroll
        for (int it = 0; it < 16; it++) {
            int job = tid + it * 128;
            int r = job & 63, c2 = job >> 6;  // r: token, c2: dim pair
            half2 v = *(const half2*)&Vs[r][c2 * 2];
            Vt[c2 * 2 + 0][r] = __low2half(v);
            Vt[c2 * 2 + 1][r] = __high2half(v);
        }

        // S = Q K^T (independent of Vt)
        float sc[8][4];
#pragma unroll
        for (int nb = 0; nb < 8; nb++) {
#pragma unroll
            for (int r = 0; r < 4; r++) sc[nb][r] = 0.0f;
#pragma unroll
            for (int ks = 0; ks < 4; ks++) {
                const half* kp = &Ks[nb * 8 + g][16 * ks + 2 * tg];
                uint32_t b0 = *(const uint32_t*)kp;
                uint32_t b1 = *(const uint32_t*)(kp + 8);
                mma16816(sc[nb], aq[ks][0], aq[ks][1], aq[ks][2], aq[ks][3], b0, b1);
            }
        }
        __syncthreads();  // Vt ready for PV

        // bias + mask + online softmax
        float b00 = bq[16 * w + g][0],     b01 = bq[16 * w + g][1];
        float b10 = bq[16 * w + g + 8][0], b11 = bq[16 * w + g + 8][1];
        float rm0 = -1e30f, rm1 = -1e30f;
#pragma unroll
        for (int nb = 0; nb < 8; nb++) {
            int kg0 = kt * 64 + nb * 8 + 2 * tg;
            int kg1 = kg0 + 1;
            float v0 = sc[nb][0] * 0.125f + (kg0 == qg0 ? b01 : b00);
            float v1 = sc[nb][1] * 0.125f + (kg1 == qg0 ? b01 : b00);
            float v2 = sc[nb][2] * 0.125f + (kg0 == qg1 ? b11 : b10);
            float v3 = sc[nb][3] * 0.125f + (kg1 == qg1 ? b11 : b10);
            if (kg0 > qg0) v0 = -1e9f;
            if (kg1 > qg0) v1 = -1e9f;
            if (kg0 > qg1) v2 = -1e9f;
            if (kg1 > qg1) v3 = -1e9f;
            sc[nb][0] = v0; sc[nb][1] = v1; sc[nb][2] = v2; sc[nb][3] = v3;
            rm0 = fmaxf(rm0, fmaxf(v0, v1));
            rm1 = fmaxf(rm1, fmaxf(v2, v3));
        }
#pragma unroll
        for (int o = 1; o < 4; o <<= 1) {
            rm0 = fmaxf(rm0, __shfl_xor_sync(0xffffffffu, rm0, o));
            rm1 = fmaxf(rm1, __shfl_xor_sync(0xffffffffu, rm1, o));
        }
        float mn0 = fmaxf(m_i[0], rm0), mn1 = fmaxf(m_i[1], rm1);
        float sc0 = __expf(m_i[0] - mn0), sc1 = __expf(m_i[1] - mn1);
        float ls0 = 0.0f, ls1 = 0.0f;
#pragma unroll
        for (int nb = 0; nb < 8; nb++) {
            sc[nb][0] = __expf(sc[nb][0] - mn0);
            sc[nb][1] = __expf(sc[nb][1] - mn0);
            sc[nb][2] = __expf(sc[nb][2] - mn1);
            sc[nb][3] = __expf(sc[nb][3] - mn1);
            ls0 += sc[nb][0] + sc[nb][1];
            ls1 += sc[nb][2] + sc[nb][3];
        }
#pragma unroll
        for (int o = 1; o < 4; o <<= 1) {
            ls0 += __shfl_xor_sync(0xffffffffu, ls0, o);
            ls1 += __shfl_xor_sync(0xffffffffu, ls1, o);
        }
        l_i[0] = l_i[0] * sc0 + ls0;
        l_i[1] = l_i[1] * sc1 + ls1;
        m_i[0] = mn0; m_i[1] = mn1;
#pragma unroll
        for (int nd = 0; nd < 8; nd++) {
            O[nd][0] *= sc0; O[nd][1] *= sc0;
            O[nd][2] *= sc1; O[nd][3] *= sc1;
        }

        // pack P into A-frags (C-frag layout == A-frag layout)
        uint32_t pa[4][4];
#pragma unroll
        for (int ks = 0; ks < 4; ks++) {
            pa[ks][0] = h2_as_u32(__floats2half2_rn(sc[2 * ks][0],     sc[2 * ks][1]));
            pa[ks][1] = h2_as_u32(__floats2half2_rn(sc[2 * ks][2],     sc[2 * ks][3]));
            pa[ks][2] = h2_as_u32(__floats2half2_rn(sc[2 * ks + 1][0], sc[2 * ks + 1][1]));
            pa[ks][3] = h2_as_u32(__floats2half2_rn(sc[2 * ks + 1][2], sc[2 * ks + 1][3]));
        }

        // O += P V  (B-frags from Vt)
#pragma unroll
        for (int nd = 0; nd < 8; nd++) {
#pragma unroll
            for (int ks = 0; ks < 4; ks++) {
                const half* vp = &Vt[nd * 8 + g][16 * ks + 2 * tg];
                uint32_t b0 = *(const uint32_t*)vp;
                uint32_t b1 = *(const uint32_t*)(vp + 8);
                mma16816(O[nd], pa[ks][0], pa[ks][1], pa[ks][2], pa[ks][3], b0, b1);
            }
        }
    }

    // epilogue: vres = values + O / l
    float inv0 = 1.0f / l_i[0], inv1 = 1.0f / l_i[1];
    size_t row0 = (size_t)(b * S_ + qt * 64 + 16 * w + g);
    size_t row1 = row0 + 8;
#pragma unroll
    for (int nd = 0; nd < 8; nd++) {
        int col = h * DIM_ + nd * 8 + 2 * tg;
        float2 v0 = *(const float2*)(values + row0 * D_ + col);
        float2 v1 = *(const float2*)(values + row1 * D_ + col);
        float2 o0 = {v0.x + O[nd][0] * inv0, v0.y + O[nd][1] * inv0};
        float2 o1 = {v1.x + O[nd][2] * inv1, v1.y + O[nd][3] * inv1};
        *(float2*)(vres + row0 * D_ + col) = o0;
        *(float2*)(vres + row1 * D_ + col) = o1;
    }
}

// ---------------------------------------------------------------------------
// Launcher
// ---------------------------------------------------------------------------
extern "C" void kernel_launch(void* const* d_in, const int* in_sizes, int n_in,
                              void* d_out, int out_size) {
    (void)in_sizes; (void)n_in; (void)out_size;
    const float* values = (const float*)d_in[0];
    const float* ln0_g  = (const float*)d_in[2];
    const float* ln0_b  = (const float*)d_in[3];
    const float* W0a    = (const float*)d_in[4];
    const float* b0a    = (const float*)d_in[5];
    const float* W0b    = (const float*)d_in[6];
    const float* b0b    = (const float*)d_in[7];
    const float* Wp     = (const float*)d_in[8];
    const float* bp     = (const float*)d_in[9];
    const float* ln1_g  = (const float*)d_in[10];
    const float* ln1_b  = (const float*)d_in[11];
    const float* W1a    = (const float*)d_in[12];
    const float* b1a    = (const float*)d_in[13];
    const float* W1b    = (const float*)d_in[14];
    const float* b1b    = (const float*)d_in[15];
    float* out = (float*)d_out;

    half *ph, *pact, *pqkv, *pwt0a, *pwt0b, *pwt1a, *pwt1b;
    float *pvres;
    cudaGetSymbolAddress((void**)&ph,    g_h);
    cudaGetSymbolAddress((void**)&pact,  g_act);
    cudaGetSymbolAddress((void**)&pqkv,  g_qkv);
    cudaGetSymbolAddress((void**)&pvres, g_vres);
    cudaGetSymbolAddress((void**)&pwt0a, g_wt0a);
    cudaGetSymbolAddress((void**)&pwt0b, g_wt0b);
    cudaGetSymbolAddress((void**)&pwt1a, g_wt1a);
    cudaGetSymbolAddress((void**)&pwt1b, g_wt1b);

    int gemm_smem = 2 * 2 * TILE_H * 2;  // 73728 bytes
    cudaFuncSetAttribute(mma_gemm<0>, cudaFuncAttributeMaxDynamicSharedMemorySize, gemm_smem);
    cudaFuncSetAttribute(mma_gemm<1>, cudaFuncAttributeMaxDynamicSharedMemorySize, gemm_smem);
    cudaFuncSetAttribute(mma_gemm<2>, cudaFuncAttributeMaxDynamicSharedMemorySize, gemm_smem);

    // 0) transpose weights to [N,K] half
    transpose_kernel<<<dim3(HID_ / 32, D_ / 32), dim3(32, 8)>>>(W0a, pwt0a, D_, HID_);
    transpose_kernel<<<dim3(QKV_N_ / 32, HID_ / 32), dim3(32, 8)>>>(W0b, pwt0b, HID_, QKV_N_);
    transpose_kernel<<<dim3(HID_ / 32, D_ / 32), dim3(32, 8)>>>(W1a, pwt1a, D_, HID_);
    transpose_kernel<<<dim3(D_ / 32, HID_ / 32), dim3(32, 8)>>>(W1b, pwt1b, HID_, D_);

    // 1) LN0 -> half
    ln_kernel<<<ROWS_, 128>>>(values, ln0_g, ln0_b, ph);
    // 2) act = relu(h @ W0a + b0a) -> half
    mma_gemm<1><<<dim3(HID_ / 128, ROWS_ / 128), 256, gemm_smem>>>(
        ph, pwt0a, b0a, nullptr, pact, HID_, D_);
    // 3) qkv = act @ W0b + b0b -> half
    mma_gemm<0><<<dim3(QKV_N_ / 128, ROWS_ / 128), 256, gemm_smem>>>(
        pact, pwt0b, b0b, nullptr, pqkv, QKV_N_, HID_);
    // 4) attention + residual -> vres (fp32)
    attn_mma_kernel<<<dim3(S_ / 64, H_, B_), 128>>>(
        pqkv, values, Wp, bp, pvres);
    // 5) LN1 -> half
    ln_kernel<<<ROWS_, 128>>>(pvres, ln1_g, ln1_b, ph);
    // 6) act = relu(h @ W1a + b1a) -> half
    mma_gemm<1><<<dim3(HID_ / 128, ROWS_ / 128), 256, gemm_smem>>>(
        ph, pwt1a, b1a, nullptr, pact, HID_, D_);
    // 7) out = vres + act @ W1b + b1b -> float
    mma_gemm<2><<<dim3(D_ / 128, ROWS_ / 128), 256, gemm_smem>>>(
        pact, pwt1b, b1b, pvres, out, D_, HID_);
}

// round 7
// speedup vs baseline: 6.2113x; 1.0735x over previous
#include <cuda_runtime.h>
#include <cuda_fp16.h>
#include <math.h>
#include <cstdint>

// Problem constants
#define B_   8
#define S_   512
#define D_   512
#define H_   8
#define HID_ 2048
#define DIM_ 64
#define ROWS_ (B_ * S_)        // 4096
#define QKV_N_ (3 * D_)        // 1536
#define EPS_ 0.001f

// ---------------------------------------------------------------------------
// Scratch (device globals; no allocation allowed)
// ---------------------------------------------------------------------------
__device__ __align__(16) half  g_h[ROWS_ * D_];        // LN output (half)
__device__ __align__(16) half  g_act[ROWS_ * HID_];    // MLP hidden (half)
__device__ __align__(16) half  g_qkv[ROWS_ * QKV_N_];  // fused qkv (half)
__device__ __align__(16) float g_vres[ROWS_ * D_];     // values + attn
// transposed weights (B^T, [N,K] K-major, half) for mma.sync
__device__ __align__(16) half g_wt0a[HID_ * D_];
__device__ __align__(16) half g_wt0b[QKV_N_ * HID_];
__device__ __align__(16) half g_wt1a[HID_ * D_];
__device__ __align__(16) half g_wt1b[D_ * HID_];

// ---------------------------------------------------------------------------
// helpers
// ---------------------------------------------------------------------------
__device__ __forceinline__ void cp_async16(uint32_t d, const void* s) {
    asm volatile("cp.async.cg.shared.global [%0], [%1], 16;"
                 :: "r"(d), "l"(s) : "memory");
}
__device__ __forceinline__ uint32_t smem_u32(const void* p) {
    uint32_t a;
    asm("{ .reg .u64 t; cvta.to.shared.u64 t, %1; cvt.u32.u64 %0, t; }"
        : "=r"(a) : "l"(p));
    return a;
}
__device__ __forceinline__ uint32_t h2_as_u32(half2 h) {
    union { half2 h; uint32_t u; } cvt;
    cvt.h = h;
    return cvt.u;
}
__device__ __forceinline__ void mma16816(float* c, uint32_t a0, uint32_t a1,
                                         uint32_t a2, uint32_t a3,
                                         uint32_t b0, uint32_t b1) {
    asm volatile(
        "mma.sync.aligned.m16n8k16.row.col.f32.f16.f16.f32 "
        "{%0,%1,%2,%3}, {%4,%5,%6,%7}, {%8,%9}, {%0,%1,%2,%3};"
        : "+f"(c[0]), "+f"(c[1]), "+f"(c[2]), "+f"(c[3])
        : "r"(a0), "r"(a1), "r"(a2), "r"(a3), "r"(b0), "r"(b1));
}
__device__ __forceinline__ void ldsm_x4(uint32_t& r0, uint32_t& r1,
                                        uint32_t& r2, uint32_t& r3,
                                        uint32_t addr) {
    asm volatile("ldmatrix.sync.aligned.m8n8.x4.shared.b16 {%0,%1,%2,%3}, [%4];"
                 : "=r"(r0), "=r"(r1), "=r"(r2), "=r"(r3) : "r"(addr));
}

// ---------------------------------------------------------------------------
// Weight transpose + fp32->fp16: src[K,N] fp32 -> dst[N,K] half
// ---------------------------------------------------------------------------
__global__ void transpose_kernel(const float* __restrict__ src,
                                 half* __restrict__ dst, int K, int N) {
    __shared__ float t[32][33];
    int bn = blockIdx.x * 32, bk = blockIdx.y * 32;
    int x = bn + threadIdx.x;
#pragma unroll
    for (int i = 0; i < 32; i += 8)
        t[threadIdx.y + i][threadIdx.x] = src[(size_t)(bk + threadIdx.y + i) * N + x];
    __syncthreads();
    int xo = bk + threadIdx.x;
#pragma unroll
    for (int i = 0; i < 32; i += 8)
        dst[(size_t)(bn + threadIdx.y + i) * K + xo] =
            __float2half_rn(t[threadIdx.x][threadIdx.y + i]);
}

// ---------------------------------------------------------------------------
// HMMA fp16 GEMM: C[M,N] = A[M,K](half) @ Bt[N,K](half)^T + bias
// BM=BN=128, BK=64, 256 threads (8 warps, 2x4), warp tile 64x32.
// ldmatrix fragment loads; double-buffered cp.async; 1 barrier per k-tile.
// EPI: 0 = bias -> half out; 1 = bias+relu -> half out; 2 = bias+res -> float
// ---------------------------------------------------------------------------
#define LDH 72
#define TILE_H (128 * LDH)
#define TILE_B (TILE_H * 2)   // bytes per tile buffer

template <int EPI>
__global__ void __launch_bounds__(256, 2)
mma_gemm(const half* __restrict__ A, const half* __restrict__ Bt,
         const float* __restrict__ bias, const float* __restrict__ res,
         void* __restrict__ Cout, int N, int K) {
    extern __shared__ char smem[];
    half* As = (half*)smem;
    half* Bs = As + 2 * TILE_H;
    uint32_t sA = smem_u32(As);
    uint32_t sB = smem_u32(Bs);

    int tid = threadIdx.x;
    int wid = tid >> 5, lane = tid & 31;
    int wm = wid >> 2, wn = wid & 3;
    int g = lane >> 2, tg = lane & 3;
    int m0 = blockIdx.y * 128, n0 = blockIdx.x * 128;

    // ldmatrix per-lane address bases (constant over k loop)
    int lt = lane >> 3, lr = lane & 7;
    // A x4 tile order: (rows, k0), (rows+8, k0), (rows, k0+8), (rows+8, k0+8)
    uint32_t a_rows = (uint32_t)((lt & 1) * 8 + lr);
    uint32_t a_col  = (uint32_t)((lt >> 1) * 8);
    uint32_t a_base = sA + ((wm * 64 + a_rows) * LDH + a_col) * 2;
    // B x4 tile order: (rows, k0), (rows, k0+8), (rows+16.., k0), (rows+16.., k0+8)
    uint32_t b_rows = (uint32_t)((lt >> 1) * 8 + lr);
    uint32_t b_col  = (uint32_t)((lt & 1) * 8);
    uint32_t b_base = sB + ((wn * 32 + b_rows) * LDH + b_col) * 2;

    float acc[4][4][4];
#pragma unroll
    for (int i = 0; i < 4; i++)
#pragma unroll
        for (int j = 0; j < 4; j++)
#pragma unroll
            for (int r = 0; r < 4; r++) acc[i][j][r] = 0.0f;

    auto load_tiles = [&](int kt, int buf) {
        uint32_t da = sA + buf * TILE_B;
        uint32_t db = sB + buf * TILE_B;
#pragma unroll
        for (int p = 0; p < 4; p++) {
            int idx = tid + p * 256;
            int r = idx >> 3, c = idx & 7;
            cp_async16(da + (r * LDH + c * 8) * 2,
                       A + (size_t)(m0 + r) * K + kt * 64 + c * 8);
        }
#pragma unroll
        for (int p = 0; p < 4; p++) {
            int idx = tid + p * 256;
            int r = idx >> 3, c = idx & 7;
            cp_async16(db + (r * LDH + c * 8) * 2,
                       Bt + (size_t)(n0 + r) * K + kt * 64 + c * 8);
        }
        asm volatile("cp.async.commit_group;" ::: "memory");
    };

    const int KT = K / 64;
    load_tiles(0, 0);

    for (int kt = 0; kt < KT; kt++) {
        int buf = kt & 1;
        asm volatile("cp.async.wait_group 0;" ::: "memory");
        __syncthreads();
        if (kt + 1 < KT) load_tiles(kt + 1, buf ^ 1);

        uint32_t ab = a_base + buf * TILE_B;
        uint32_t bb = b_base + buf * TILE_B;
#pragma unroll
        for (int ks = 0; ks < 4; ks++) {
            uint32_t koff = ks * 32;  // 16 halves
            uint32_t breg[4][2];
#pragma unroll
            for (int j = 0; j < 2; j++)
                ldsm_x4(breg[2 * j][0], breg[2 * j][1],
                        breg[2 * j + 1][0], breg[2 * j + 1][1],
                        bb + j * (16 * LDH * 2) + koff);
#pragma unroll
            for (int ma = 0; ma < 4; ma++) {
                uint32_t a0, a1, a2, a3;
                ldsm_x4(a0, a1, a2, a3, ab + ma * (16 * LDH * 2) + koff);
#pragma unroll
                for (int na = 0; na < 4; na++)
                    mma16816(acc[ma][na], a0, a1, a2, a3, breg[na][0], breg[na][1]);
            }
        }
    }

#pragma unroll
    for (int na = 0; na < 4; na++) {
        int col = n0 + wn * 32 + na * 8 + 2 * tg;
        float2 bb = *(const float2*)(bias + col);
#pragma unroll
        for (int ma = 0; ma < 4; ma++) {
            int row = m0 + wm * 64 + ma * 16 + g;
            float x0 = acc[ma][na][0] + bb.x;
            float x1 = acc[ma][na][1] + bb.y;
            float x2 = acc[ma][na][2] + bb.x;
            float x3 = acc[ma][na][3] + bb.y;
            if (EPI == 1) {
                x0 = fmaxf(x0, 0.0f); x1 = fmaxf(x1, 0.0f);
                x2 = fmaxf(x2, 0.0f); x3 = fmaxf(x3, 0.0f);
            }
            if (EPI == 0 || EPI == 1) {
                half* C = (half*)Cout;
                *(half2*)(C + (size_t)row * N + col)       = __floats2half2_rn(x0, x1);
                *(half2*)(C + (size_t)(row + 8) * N + col) = __floats2half2_rn(x2, x3);
            } else {
                float* C = (float*)Cout;
                float2 r0 = *(const float2*)(res + (size_t)row * N + col);
                float2 r1 = *(const float2*)(res + (size_t)(row + 8) * N + col);
                float2 v0 = {x0 + r0.x, x1 + r0.y};
                float2 v1 = {x2 + r1.x, x3 + r1.y};
                *(float2*)(C + (size_t)row * N + col) = v0;
                *(float2*)(C + (size_t)(row + 8) * N + col) = v1;
            }
        }
    }
}

// ---------------------------------------------------------------------------
// LayerNorm: one block per row, 128 threads, D=512; outputs HALF
// ---------------------------------------------------------------------------
__global__ void ln_kernel(const float* __restrict__ x,
                          const float* __restrict__ g,
                          const float* __restrict__ b,
                          half* __restrict__ y) {
    int row = blockIdx.x;
    int t   = threadIdx.x;
    const float4* xr = (const float4*)(x + (size_t)row * D_);
    float4 v = xr[t];
    float s  = v.x + v.y + v.z + v.w;
    float ss = v.x * v.x + v.y * v.y + v.z * v.z + v.w * v.w;
#pragma unroll
    for (int o = 16; o; o >>= 1) {
        s  += __shfl_xor_sync(0xffffffffu, s,  o);
        ss += __shfl_xor_sync(0xffffffffu, ss, o);
    }
    __shared__ float sm[4], sm2[4];
    int w = t >> 5;
    if ((t & 31) == 0) { sm[w] = s; sm2[w] = ss; }
    __syncthreads();
    float tot = sm[0] + sm[1] + sm[2] + sm[3];
    float tot2 = sm2[0] + sm2[1] + sm2[2] + sm2[3];
    float mean = tot * (1.0f / D_);
    float var  = tot2 * (1.0f / D_) - mean * mean;
    float rstd = rsqrtf(var + EPS_);

    int c = t * 4;
    float4 gv = *(const float4*)(g + c);
    float4 bv = *(const float4*)(b + c);
    half* yr = y + (size_t)row * D_ + c;
    *(half2*)(yr)     = __floats2half2_rn((v.x - mean) * rstd * gv.x + bv.x,
                                          (v.y - mean) * rstd * gv.y + bv.y);
    *(half2*)(yr + 2) = __floats2half2_rn((v.z - mean) * rstd * gv.z + bv.z,
                                          (v.w - mean) * rstd * gv.w + bv.w);
}

// ---------------------------------------------------------------------------
// HMMA flash attention with relative-position bias (NUM_POS=1, causal).
// ---------------------------------------------------------------------------
#define ALD 72
#define VLD 72

__global__ void __launch_bounds__(128)
attn_mma_kernel(const half* __restrict__ qkv, const float* __restrict__ values,
                const float* __restrict__ Wp, const float* __restrict__ bp,
                float* __restrict__ vres) {
    __shared__ half Qs[64][ALD];
    __shared__ half Ks[64][ALD];
    __shared__ half Vs[64][VLD];
    __shared__ half Vt[64][ALD];
    __shared__ float bq[64][2];

    int qt = blockIdx.x, h = blockIdx.y, b = blockIdx.z;
    int tid = threadIdx.x;
    int w = tid >> 5, lane = tid & 31;
    int g = lane >> 2, tg = lane & 3;

#pragma unroll
    for (int it = 0; it < 4; it++) {
        int job = tid + it * 128;
        int r = job >> 3, c = job & 7;
        *(uint4*)&Qs[r][c * 8] = *(const uint4*)(
            qkv + (size_t)(b * S_ + qt * 64 + r) * QKV_N_ + h * 192 + c * 8);
    }
    __syncthreads();

    {
        int row = tid >> 1, m = tid & 1;
        float s = 0.0f;
        const float* wrow = Wp + m * D_ + h * DIM_;
        const float* brow = bp + h * DIM_;
#pragma unroll 8
        for (int d = 0; d < 64; d++)
            s += __half2float(Qs[row][d]) * (wrow[d] + brow[d]);
        bq[row][m] = s;
    }

    uint32_t aq[4][4];
#pragma unroll
    for (int ks = 0; ks < 4; ks++) {
        const half* ap = &Qs[16 * w + g][16 * ks + 2 * tg];
        aq[ks][0] = *(const uint32_t*)ap;
        aq[ks][1] = *(const uint32_t*)(ap + 8 * ALD);
        aq[ks][2] = *(const uint32_t*)(ap + 8);
        aq[ks][3] = *(const uint32_t*)(ap + 8 * ALD + 8);
    }

    float m_i[2] = {-1e30f, -1e30f};
    float l_i[2] = {0.0f, 0.0f};
    float O[8][4];
#pragma unroll
    for (int nd = 0; nd < 8; nd++)
#pragma unroll
        for (int r = 0; r < 4; r++) O[nd][r] = 0.0f;

    int qg0 = qt * 64 + 16 * w + g;
    int qg1 = qg0 + 8;

    for (int kt = 0; kt <= qt; kt++) {
        __syncthreads();
#pragma unroll
        for (int it = 0; it < 4; it++) {
            int job = tid + it * 128;
            int r = job >> 3, c = job & 7;
            const half* base = qkv + (size_t)(b * S_ + kt * 64 + r) * QKV_N_ + h * 192;
            *(uint4*)&Ks[r][c * 8] = *(const uint4*)(base + 64 + c * 8);
            *(uint4*)&Vs[r][c * 8] = *(const uint4*)(base + 128 + c * 8);
        }
        __syncthreads();

#pragma unroll
        for (int it = 0; it < 16; it++) {
            int job = tid + it * 128;
            int r = job & 63, c2 = job >> 6;
            half2 v = *(const half2*)&Vs[r][c2 * 2];
            Vt[c2 * 2 + 0][r] = __low2half(v);
            Vt[c2 * 2 + 1][r] = __high2half(v);
        }

        float sc[8][4];
#pragma unroll
        for (int nb = 0; nb < 8; nb++) {
#pragma unroll
            for (int r = 0; r < 4; r++) sc[nb][r] = 0.0f;
#pragma unroll
            for (int ks = 0; ks < 4; ks++) {
                const half* kp = &Ks[nb * 8 + g][16 * ks + 2 * tg];
                uint32_t b0 = *(const uint32_t*)kp;
                uint32_t b1 = *(const uint32_t*)(kp + 8);
                mma16816(sc[nb], aq[ks][0], aq[ks][1], aq[ks][2], aq[ks][3], b0, b1);
            }
        }
        __syncthreads();

        float b00 = bq[16 * w + g][0],     b01 = bq[16 * w + g][1];
        float b10 = bq[16 * w + g + 8][0], b11 = bq[16 * w + g + 8][1];
        float rm0 = -1e30f, rm1 = -1e30f;
#pragma unroll
        for (int nb = 0; nb < 8; nb++) {
            int kg0 = kt * 64 + nb * 8 + 2 * tg;
            int kg1 = kg0 + 1;
            float v0 = sc[nb][0] * 0.125f + (kg0 == qg0 ? b01 : b00);
            float v1 = sc[nb][1] * 0.125f + (kg1 == qg0 ? b01 : b00);
            float v2 = sc[nb][2] * 0.125f + (kg0 == qg1 ? b11 : b10);
            float v3 = sc[nb][3] * 0.125f + (kg1 == qg1 ? b11 : b10);
            if (kg0 > qg0) v0 = -1e9f;
            if (kg1 > qg0) v1 = -1e9f;
            if (kg0 > qg1) v2 = -1e9f;
            if (kg1 > qg1) v3 = -1e9f;
            sc[nb][0] = v0; sc[nb][1] = v1; sc[nb][2] = v2; sc[nb][3] = v3;
            rm0 = fmaxf(rm0, fmaxf(v0, v1));
            rm1 = fmaxf(rm1, fmaxf(v2, v3));
        }
#pragma unroll
        for (int o = 1; o < 4; o <<= 1) {
            rm0 = fmaxf(rm0, __shfl_xor_sync(0xffffffffu, rm0, o));
            rm1 = fmaxf(rm1, __shfl_xor_sync(0xffffffffu, rm1, o));
        }
        float mn0 = fmaxf(m_i[0], rm0), mn1 = fmaxf(m_i[1], rm1);
        float sc0 = __expf(m_i[0] - mn0), sc1 = __expf(m_i[1] - mn1);
        float ls0 = 0.0f, ls1 = 0.0f;
#pragma unroll
        for (int nb = 0; nb < 8; nb++) {
            sc[nb][0] = __expf(sc[nb][0] - mn0);
            sc[nb][1] = __expf(sc[nb][1] - mn0);
            sc[nb][2] = __expf(sc[nb][2] - mn1);
            sc[nb][3] = __expf(sc[nb][3] - mn1);
            ls0 += sc[nb][0] + sc[nb][1];
            ls1 += sc[nb][2] + sc[nb][3];
        }
#pragma unroll
        for (int o = 1; o < 4; o <<= 1) {
            ls0 += __shfl_xor_sync(0xffffffffu, ls0, o);
            ls1 += __shfl_xor_sync(0xffffffffu, ls1, o);
        }
        l_i[0] = l_i[0] * sc0 + ls0;
        l_i[1] = l_i[1] * sc1 + ls1;
        m_i[0] = mn0; m_i[1] = mn1;
#pragma unroll
        for (int nd = 0; nd < 8; nd++) {
            O[nd][0] *= sc0; O[nd][1] *= sc0;
            O[nd][2] *= sc1; O[nd][3] *= sc1;
        }

        uint32_t pa[4][4];
#pragma unroll
        for (int ks = 0; ks < 4; ks++) {
            pa[ks][0] = h2_as_u32(__floats2half2_rn(sc[2 * ks][0],     sc[2 * ks][1]));
            pa[ks][1] = h2_as_u32(__floats2half2_rn(sc[2 * ks][2],     sc[2 * ks][3]));
            pa[ks][2] = h2_as_u32(__floats2half2_rn(sc[2 * ks + 1][0], sc[2 * ks + 1][1]));
            pa[ks][3] = h2_as_u32(__floats2half2_rn(sc[2 * ks + 1][2], sc[2 * ks + 1][3]));
        }

#pragma unroll
        for (int nd = 0; nd < 8; nd++) {
#pragma unroll
            for (int ks = 0; ks < 4; ks++) {
                const half* vp = &Vt[nd * 8 + g][16 * ks + 2 * tg];
                uint32_t b0 = *(const uint32_t*)vp;
                uint32_t b1 = *(const uint32_t*)(vp + 8);
                mma16816(O[nd], pa[ks][0], pa[ks][1], pa[ks][2], pa[ks][3], b0, b1);
            }
        }
    }

    float inv0 = 1.0f / l_i[0], inv1 = 1.0f / l_i[1];
    size_t row0 = (size_t)(b * S_ + qt * 64 + 16 * w + g);
    size_t row1 = row0 + 8;
#pragma unroll
    for (int nd = 0; nd < 8; nd++) {
        int col = h * DIM_ + nd * 8 + 2 * tg;
        float2 v0 = *(const float2*)(values + row0 * D_ + col);
        float2 v1 = *(const float2*)(values + row1 * D_ + col);
        float2 o0 = {v0.x + O[nd][0] * inv0, v0.y + O[nd][1] * inv0};
        float2 o1 = {v1.x + O[nd][2] * inv1, v1.y + O[nd][3] * inv1};
        *(float2*)(vres + row0 * D_ + col) = o0;
        *(float2*)(vres + row1 * D_ + col) = o1;
    }
}

// ---------------------------------------------------------------------------
// Launcher
// ---------------------------------------------------------------------------
extern "C" void kernel_launch(void* const* d_in, const int* in_sizes, int n_in,
                              void* d_out, int out_size) {
    (void)in_sizes; (void)n_in; (void)out_size;
    const float* values = (const float*)d_in[0];
    const float* ln0_g  = (const float*)d_in[2];
    const float* ln0_b  = (const float*)d_in[3];
    const float* W0a    = (const float*)d_in[4];
    const float* b0a    = (const float*)d_in[5];
    const float* W0b    = (const float*)d_in[6];
    const float* b0b    = (const float*)d_in[7];
    const float* Wp     = (const float*)d_in[8];
    const float* bp     = (const float*)d_in[9];
    const float* ln1_g  = (const float*)d_in[10];
    const float* ln1_b  = (const float*)d_in[11];
    const float* W1a    = (const float*)d_in[12];
    const float* b1a    = (const float*)d_in[13];
    const float* W1b    = (const float*)d_in[14];
    const float* b1b    = (const float*)d_in[15];
    float* out = (float*)d_out;

    half *ph, *pact, *pqkv, *pwt0a, *pwt0b, *pwt1a, *pwt1b;
    float *pvres;
    cudaGetSymbolAddress((void**)&ph,    g_h);
    cudaGetSymbolAddress((void**)&pact,  g_act);
    cudaGetSymbolAddress((void**)&pqkv,  g_qkv);
    cudaGetSymbolAddress((void**)&pvres, g_vres);
    cudaGetSymbolAddress((void**)&pwt0a, g_wt0a);
    cudaGetSymbolAddress((void**)&pwt0b, g_wt0b);
    cudaGetSymbolAddress((void**)&pwt1a, g_wt1a);
    cudaGetSymbolAddress((void**)&pwt1b, g_wt1b);

    int gemm_smem = 2 * 2 * TILE_H * 2;  // 73728 bytes
    cudaFuncSetAttribute(mma_gemm<0>, cudaFuncAttributeMaxDynamicSharedMemorySize, gemm_smem);
    cudaFuncSetAttribute(mma_gemm<1>, cudaFuncAttributeMaxDynamicSharedMemorySize, gemm_smem);
    cudaFuncSetAttribute(mma_gemm<2>, cudaFuncAttributeMaxDynamicSharedMemorySize, gemm_smem);

    // 0) transpose weights to [N,K] half
    transpose_kernel<<<dim3(HID_ / 32, D_ / 32), dim3(32, 8)>>>(W0a, pwt0a, D_, HID_);
    transpose_kernel<<<dim3(QKV_N_ / 32, HID_ / 32), dim3(32, 8)>>>(W0b, pwt0b, HID_, QKV_N_);
    transpose_kernel<<<dim3(HID_ / 32, D_ / 32), dim3(32, 8)>>>(W1a, pwt1a, D_, HID_);
    transpose_kernel<<<dim3(D_ / 32, HID_ / 32), dim3(32, 8)>>>(W1b, pwt1b, HID_, D_);

    // 1) LN0 -> half
    ln_kernel<<<ROWS_, 128>>>(values, ln0_g, ln0_b, ph);
    // 2) act = relu(h @ W0a + b0a) -> half
    mma_gemm<1><<<dim3(HID_ / 128, ROWS_ / 128), 256, gemm_smem>>>(
        ph, pwt0a, b0a, nullptr, pact, HID_, D_);
    // 3) qkv = act @ W0b + b0b -> half
    mma_gemm<0><<<dim3(QKV_N_ / 128, ROWS_ / 128), 256, gemm_smem>>>(
        pact, pwt0b, b0b, nullptr, pqkv, QKV_N_, HID_);
    // 4) attention + residual -> vres (fp32)
    attn_mma_kernel<<<dim3(S_ / 64, H_, B_), 128>>>(
        pqkv, values, Wp, bp, pvres);
    // 5) LN1 -> half
    ln_kernel<<<ROWS_, 128>>>(pvres, ln1_g, ln1_b, ph);
    // 6) act = relu(h @ W1a + b1a) -> half
    mma_gemm<1><<<dim3(HID_ / 128, ROWS_ / 128), 256, gemm_smem>>>(
        ph, pwt1a, b1a, nullptr, pact, HID_, D_);
    // 7) out = vres + act @ W1b + b1b -> float
    mma_gemm<2><<<dim3(D_ / 128, ROWS_ / 128), 256, gemm_smem>>>(
        pact, pwt1b, b1b, pvres, out, D_, HID_);
}